// round 8
// baseline (speedup 1.0000x reference)
#include <cuda_runtime.h>
#include <math.h>
#include <stdint.h>

#define NTHREADS 256
#define PAIRS    16
#define ROWS     48
#define NBLK     2048

typedef unsigned long long ull;

// fused-kernel smem layout (floats): 18816 floats -> 3 blocks/SM
#define EVT_OFF   0
#define FEAT_OFF  8448
#define ABUF_OFF  14592
#define SMEM_FLOATS 18816
#define SMEM_BYTES (SMEM_FLOATS*4)
#define GH1_OFF   (EVT_OFF + 0)
#define GH2_OFF   (EVT_OFF + 3072)
#define TGTB_OFF  (EVT_OFF + 0)
#define WQ_OFF    (EVT_OFF + 4096)
#define WP_OFF    (EVT_OFF + 0)
#define OUTB_OFF  (ABUF_OFF + 0)
#define SC_OFF    (ABUF_OFF + 2048)
#define HB_OFF    (FEAT_OFF + 0)
#define SF_OFF    (FEAT_OFF + 1024)
#define XB_OFF    (FEAT_OFF + 2048)
#define H1_OFF    (FEAT_OFF + 3264)
#define H2_OFF    (FEAT_OFF + 4480)

__device__ __forceinline__ ull pack2(float lo, float hi) {
    ull r; asm("mov.b64 %0, {%1, %2};" : "=l"(r) : "f"(lo), "f"(hi)); return r;
}
__device__ __forceinline__ void unpack2(ull v, float& lo, float& hi) {
    asm("mov.b64 {%0, %1}, %2;" : "=f"(lo), "=f"(hi) : "l"(v));
}
__device__ __forceinline__ void fma2(ull& d, ull a, ull b) {
    asm("fma.rn.f32x2 %0, %1, %2, %0;" : "+l"(d) : "l"(a), "l"(b));
}
__device__ __forceinline__ float fsel4(float4 v, int kk) {
    return (kk==0)?v.x:(kk==1)?v.y:(kk==2)?v.z:v.w;
}
__device__ __forceinline__ float to_tf32(float x) {
    float r; asm("cvt.rna.tf32.f32 %0, %1;" : "=f"(r) : "f"(x)); return r;
}

// warp-level tf32 MMA (sm_80 base ISA -> compiles at compute_103)
__device__ __forceinline__ void mma_tf32(float* d,
    uint32_t a0, uint32_t a1, uint32_t a2, uint32_t a3,
    uint32_t b0, uint32_t b1)
{
    asm volatile(
        "mma.sync.aligned.m16n8k8.row.col.f32.tf32.tf32.f32 "
        "{%0,%1,%2,%3}, {%4,%5,%6,%7}, {%8,%9}, {%0,%1,%2,%3};"
        : "+f"(d[0]), "+f"(d[1]), "+f"(d[2]), "+f"(d[3])
        : "r"(a0), "r"(a1), "r"(a2), "r"(a3), "r"(b0), "r"(b1));
}

// device globals
__device__ __align__(16) float g_evt[98304*176];
__device__ __align__(16) float g_Wevt_hi[192*352];   // [n][k], zero padded, tf32 hi
__device__ __align__(16) float g_Wevt_lo[192*352];   // tf32 lo
__device__ __align__(16) float g_WT_gcn1 [176*64];   // [k][o]
__device__ __align__(16) float g_WT_gcn2 [ 64*64];
__device__ __align__(16) float g_WT_att1 [128*128];
__device__ __align__(16) float g_WT_att2 [128*128];
__device__ __align__(16) float g_WT_m1   [128*64];
__device__ __align__(16) float g_WT_m2   [ 64*64];

__global__ void prep_kernel(const float* __restrict__ ew,
                            const float* __restrict__ g1,
                            const float* __restrict__ g2,
                            const float* __restrict__ a1,
                            const float* __restrict__ a2,
                            const float* __restrict__ m1,
                            const float* __restrict__ m2)
{
    int t0 = blockIdx.x*blockDim.x + threadIdx.x;
    int stride = gridDim.x*blockDim.x;
    for (int i = t0; i < 192*352; i += stride) {
        int n = i/352, k = i - n*352;
        float w = (n < 172 && k < 347) ? ew[n*347 + k] : 0.f;
        float h = to_tf32(w);
        g_Wevt_hi[i] = h;
        g_Wevt_lo[i] = to_tf32(w - h);
    }
    for (int i = t0; i < 176*64; i += stride) {
        int k = i/64, o = i%64;
        g_WT_gcn1[i] = (k < 172) ? g1[o*172 + k] : 0.f;
    }
    for (int i = t0; i < 64*64; i += stride) {
        int k = i/64, o = i%64;
        g_WT_gcn2[i] = g2[o*64 + k];
        g_WT_m2[i]   = m2[o*64 + k];
    }
    for (int i = t0; i < 128*128; i += stride) {
        int k = i/128, o = i%128;
        g_WT_att1[i] = a1[o*128 + k];
        g_WT_att2[i] = a2[o*128 + k];
    }
    for (int i = t0; i < 128*64; i += stride) {
        int k = i/64, o = i%64;
        g_WT_m1[i] = m1[o*128 + k];
    }
}

// ---------------------------------------------------------------------------
// Event linear via mma.sync tf32 (3xTF32):
//   g_evt[98304, 172] = event_f[98304, 347] @ W^T + bias
// Block: 256 thr (8 warps), tile M=128 (16 rows/warp), N=96 (grid.y half),
// K=352 in chunks of 32. A generated on the fly.
// smem pitch 36 floats -> bank (4*(lane>>2)+(lane&3)) is a 0..31 permutation.
// ---------------------------------------------------------------------------
#define EK_THREADS 256
#define EK_MT 128
#define EK_NT 96
#define EK_K  352
#define EK_KC 32
#define SA_H  0
#define SA_L  (SA_H + EK_MT*36)
#define SB_H  (SA_L + EK_MT*36)
#define SB_L  (SB_H + EK_NT*36)
#define EV_SMEM_FLOATS (SB_L + EK_NT*36)      // 16128 floats = 64512 B
#define EV_SMEM_BYTES (EV_SMEM_FLOATS*4)

__global__ void __launch_bounds__(EK_THREADS, 2)
event_mma_kernel(const int*   __restrict__ edge_idx,
                 const float* __restrict__ edge_embed,
                 const float* __restrict__ edge_identify,
                 const float* __restrict__ t_records,
                 const float* __restrict__ basis_freq,
                 const float* __restrict__ phase,
                 const float* __restrict__ lin_event_b)
{
    extern __shared__ float smf[];
    float* Ah = smf + SA_H;
    float* Al = smf + SA_L;
    float* Bh = smf + SB_H;
    float* Bl = smf + SB_L;

    const int tid  = threadIdx.x;
    const int wid  = tid >> 5, lane = tid & 31;
    const int gq   = lane >> 2, tq = lane & 3;
    const int m0   = blockIdx.x * EK_MT;
    const int n0   = blockIdx.y * EK_NT;
    const int wm   = wid * 16;

    float acc[12][4];
#pragma unroll
    for (int j = 0; j < 12; j++)
#pragma unroll
        for (int q = 0; q < 4; q++) acc[j][q] = 0.f;

#pragma unroll 1
    for (int kc = 0; kc < EK_K; kc += EK_KC) {
        // generate A chunk (event_f), tf32 hi/lo
        for (int i = tid; i < EK_MT*EK_KC; i += EK_THREADS) {
            int r = i >> 5, kk = i & 31;
            int k = kc + kk;
            int R = m0 + r;
            int g = R / 3, l = R - g*3;
            float v = 0.f;
            if (k < 172) {
                int e = __ldg(&edge_idx[g*3 + l]);
                v = __ldg(&edge_embed[(long)e*172 + k]);
            } else if (k < 175) {
                v = __ldg(&edge_identify[(g*3 + l)*3 + (k - 172)]);
            } else if (k < 347) {
                int d = k - 175;
                float dt = __ldg(&t_records[g*3 + 2]) - __ldg(&t_records[g*3 + l]);
                v = __cosf(dt * __ldg(&basis_freq[d]) + __ldg(&phase[d]));
            }
            float hi = to_tf32(v);
            Ah[r*36 + kk] = hi;
            Al[r*36 + kk] = to_tf32(v - hi);
        }
        // stage B chunk (weights), [n][36]
        for (int i = tid; i < EK_NT*EK_KC; i += EK_THREADS) {
            int n = i >> 5, kk = i & 31;
            Bh[n*36 + kk] = g_Wevt_hi[(n0 + n)*352 + kc + kk];
            Bl[n*36 + kk] = g_Wevt_lo[(n0 + n)*352 + kc + kk];
        }
        __syncthreads();
#pragma unroll
        for (int s = 0; s < 4; s++) {
            int kb = s*8 + tq;
            uint32_t a0h = __float_as_uint(Ah[(wm+gq  )*36 + kb]);
            uint32_t a1h = __float_as_uint(Ah[(wm+gq+8)*36 + kb]);
            uint32_t a2h = __float_as_uint(Ah[(wm+gq  )*36 + kb + 4]);
            uint32_t a3h = __float_as_uint(Ah[(wm+gq+8)*36 + kb + 4]);
            uint32_t a0l = __float_as_uint(Al[(wm+gq  )*36 + kb]);
            uint32_t a1l = __float_as_uint(Al[(wm+gq+8)*36 + kb]);
            uint32_t a2l = __float_as_uint(Al[(wm+gq  )*36 + kb + 4]);
            uint32_t a3l = __float_as_uint(Al[(wm+gq+8)*36 + kb + 4]);
#pragma unroll
            for (int j = 0; j < 12; j++) {
                uint32_t b0h = __float_as_uint(Bh[(j*8+gq)*36 + kb]);
                uint32_t b1h = __float_as_uint(Bh[(j*8+gq)*36 + kb + 4]);
                uint32_t b0l = __float_as_uint(Bl[(j*8+gq)*36 + kb]);
                uint32_t b1l = __float_as_uint(Bl[(j*8+gq)*36 + kb + 4]);
                mma_tf32(acc[j], a0h, a1h, a2h, a3h, b0h, b1h);
                mma_tf32(acc[j], a0h, a1h, a2h, a3h, b0l, b1l);
                mma_tf32(acc[j], a0l, a1l, a2l, a3l, b0h, b1h);
            }
        }
        __syncthreads();
    }

    // epilogue: fragment-direct stores (+bias). col even, col<172 => col+1<172.
#pragma unroll
    for (int j = 0; j < 12; j++) {
        int col = n0 + j*8 + 2*tq;
        if (col < 172) {
            float b0 = __ldg(&lin_event_b[col]);
            float b1 = __ldg(&lin_event_b[col+1]);
            long r0 = m0 + wm + gq;
            *reinterpret_cast<float2*>(&g_evt[r0*176 + col]) =
                make_float2(acc[j][0] + b0, acc[j][1] + b1);
            *reinterpret_cast<float2*>(&g_evt[(r0+8)*176 + col]) =
                make_float2(acc[j][2] + b0, acc[j][3] + b1);
        }
    }
}

// ---------------------------------------------------------------------------
// scalar GEMM core (R6)
// ---------------------------------------------------------------------------
template<int NS, int K, int RT, int P, bool RELU, int NREAL>
__device__ __forceinline__ void gemm_direct(
    const float* __restrict__ Wg, const float* __restrict__ bias,
    const float* __restrict__ A, int sa,
    float* __restrict__ C, int sc, int tid)
{
    const int ty = tid >> 5, tx = tid & 31;
    ull acc[RT][P];
#pragma unroll
    for (int i = 0; i < RT; i++)
#pragma unroll
        for (int g = 0; g < P; g++) acc[i][g] = 0ull;
    const float* wq   = Wg + 2*tx;
    const float* arow = A + ty*RT*sa;
#pragma unroll 1
    for (int k4 = 0; k4 < K; k4 += 4) {
        ull w[4][P];
#pragma unroll
        for (int kk = 0; kk < 4; kk++)
#pragma unroll
            for (int g = 0; g < P; g++)
                w[kk][g] = __ldg(reinterpret_cast<const ull*>(wq + (k4+kk)*NS + g*64));
        float4 av[RT];
#pragma unroll
        for (int i = 0; i < RT; i++)
            av[i] = *reinterpret_cast<const float4*>(arow + i*sa + k4);
#pragma unroll
        for (int kk = 0; kk < 4; kk++)
#pragma unroll
            for (int i = 0; i < RT; i++) {
                ull ad = pack2(fsel4(av[i],kk), fsel4(av[i],kk));
#pragma unroll
                for (int g = 0; g < P; g++) fma2(acc[i][g], ad, w[kk][g]);
            }
    }
#pragma unroll
    for (int i = 0; i < RT; i++)
#pragma unroll
        for (int g = 0; g < P; g++) {
            int col = g*64 + 2*tx;
            float x, y; unpack2(acc[i][g], x, y);
            int row = ty*RT + i;
            if (col < NREAL) {
                float v = x + __ldg(&bias[col]);
                if (RELU) v = fmaxf(v, 0.f);
                C[row*sc + col] = v;
            }
            if (col + 1 < NREAL) {
                float v = y + __ldg(&bias[col+1]);
                if (RELU) v = fmaxf(v, 0.f);
                C[row*sc + col + 1] = v;
            }
        }
    __syncthreads();
}

struct GineDualGen {
    const int*   node_idx;
    const float* node_embed;
    int g0;
    __device__ __forceinline__ void operator()(float* Abuf, int kc, int tid) const {
        for (int idx = tid; idx < ROWS*44; idx += NTHREADS) {
            int r = idx / 44, cc = idx - r*44;
            int c = kc + cc;
            int p = r / 3, l = r - p*3;
            int g = g0 + p;
            float v1 = 0.f, v2 = 0.f;
            if (c < 172) {
                int ns = __ldg(&node_idx[g*6 + 2*l]);
                int nt = __ldg(&node_idx[g*6 + 2*l + 1]);
                float s = __ldg(&node_embed[(long)ns*172 + c]);
                float t = __ldg(&node_embed[(long)nt*172 + c]);
                float e = g_evt[(long)(g0*3 + r)*176 + c];
                v1 = s + fmaxf(t + e, 0.f);
                v2 = t + fmaxf(s + e, 0.f);
            }
            Abuf[idx]        = v1;
            Abuf[2112 + idx] = v2;
        }
    }
};

__device__ __forceinline__ void gemm_gine_dual(
    const float* __restrict__ bias,
    float* __restrict__ Abuf, const GineDualGen& gen,
    float* __restrict__ C1, float* __restrict__ C2, int tid)
{
    const int ty = tid >> 5, tx = tid & 31;
    ull acc1[6], acc2[6];
#pragma unroll
    for (int i = 0; i < 6; i++) { acc1[i] = 0ull; acc2[i] = 0ull; }
#pragma unroll 1
    for (int kc = 0; kc < 176; kc += 44) {
        __syncthreads();
        gen(Abuf, kc, tid);
        __syncthreads();
        const float* wq = g_WT_gcn1 + kc*64 + 2*tx;
        const float* a1row = Abuf + ty*6*44;
        const float* a2row = Abuf + 2112 + ty*6*44;
#pragma unroll 1
        for (int k4 = 0; k4 < 44; k4 += 4) {
            ull w[4];
#pragma unroll
            for (int kk = 0; kk < 4; kk++)
                w[kk] = __ldg(reinterpret_cast<const ull*>(wq + (k4+kk)*64));
#pragma unroll
            for (int i = 0; i < 6; i++) {
                float4 a1 = *reinterpret_cast<const float4*>(a1row + i*44 + k4);
                float4 a2 = *reinterpret_cast<const float4*>(a2row + i*44 + k4);
#pragma unroll
                for (int kk = 0; kk < 4; kk++) {
                    fma2(acc1[i], pack2(fsel4(a1,kk), fsel4(a1,kk)), w[kk]);
                    fma2(acc2[i], pack2(fsel4(a2,kk), fsel4(a2,kk)), w[kk]);
                }
            }
        }
    }
    int col = 2*tx;
    float b0 = __ldg(&bias[col]), b1 = __ldg(&bias[col+1]);
#pragma unroll
    for (int i = 0; i < 6; i++) {
        int row = ty*6 + i;
        float x, y;
        unpack2(acc1[i], x, y);
        C1[row*64 + col]     = fmaxf(x + b0, 0.f);
        C1[row*64 + col + 1] = fmaxf(y + b1, 0.f);
        unpack2(acc2[i], x, y);
        C2[row*64 + col]     = fmaxf(x + b0, 0.f);
        C2[row*64 + col + 1] = fmaxf(y + b1, 0.f);
    }
    __syncthreads();
}

__device__ __forceinline__ void gemm_gcn2_dual(
    const float* __restrict__ bias,
    const float* __restrict__ H1, const float* __restrict__ H2,
    float* __restrict__ feat, int tid)
{
    const int ty = tid >> 5, tx = tid & 31;
    ull acc1[6], acc2[6];
#pragma unroll
    for (int i = 0; i < 6; i++) { acc1[i] = 0ull; acc2[i] = 0ull; }
    const float* wq = g_WT_gcn2 + 2*tx;
#pragma unroll 1
    for (int k4 = 0; k4 < 64; k4 += 4) {
        ull w[4];
#pragma unroll
        for (int kk = 0; kk < 4; kk++)
            w[kk] = __ldg(reinterpret_cast<const ull*>(wq + (k4+kk)*64));
#pragma unroll
        for (int i = 0; i < 6; i++) {
            float4 a1 = *reinterpret_cast<const float4*>(H1 + (ty*6+i)*64 + k4);
            float4 a2 = *reinterpret_cast<const float4*>(H2 + (ty*6+i)*64 + k4);
#pragma unroll
            for (int kk = 0; kk < 4; kk++) {
                fma2(acc1[i], pack2(fsel4(a1,kk), fsel4(a1,kk)), w[kk]);
                fma2(acc2[i], pack2(fsel4(a2,kk), fsel4(a2,kk)), w[kk]);
            }
        }
    }
    __syncthreads();
    int col = 2*tx;
    float b0 = __ldg(&bias[col]), b1 = __ldg(&bias[col+1]);
#pragma unroll
    for (int i = 0; i < 6; i++) {
        int row = ty*6 + i;
        float x, y;
        unpack2(acc1[i], x, y);
        feat[row*128 + col]      = x + b0;
        feat[row*128 + col + 1]  = y + b1;
        unpack2(acc2[i], x, y);
        feat[row*128 + 64 + col]     = x + b0;
        feat[row*128 + 64 + col + 1] = y + b1;
    }
    __syncthreads();
}

__global__ void __launch_bounds__(NTHREADS, 3)
fused_kernel(const int*   __restrict__ node_idx,
             const int*   __restrict__ cat_feat,
             const float* __restrict__ node_embed,
             const float* __restrict__ gcn_b1,
             const float* __restrict__ gcn_b2,
             const float* __restrict__ att_w1_b,
             const float* __restrict__ att_w2_b,
             const float* __restrict__ att_m1_b,
             const float* __restrict__ att_m2_b,
             const float* __restrict__ mlp_w1,
             const float* __restrict__ mlp_b1,
             const float* __restrict__ mlp_w2,
             const float* __restrict__ mlp_b2,
             const float* __restrict__ mlp_w3,
             const float* __restrict__ mlp_b3,
             float*       __restrict__ out)
{
    extern __shared__ float sm[];
    const int tid = threadIdx.x;
    const int g0  = blockIdx.x * PAIRS;

    float* feat = sm + FEAT_OFF;
    float* Abuf = sm + ABUF_OFF;

    GineDualGen gg{node_idx, node_embed, g0};
    gemm_gine_dual(gcn_b1, Abuf, gg, sm + GH1_OFF, sm + GH2_OFF, tid);
    gemm_gcn2_dual(gcn_b2, sm + GH1_OFF, sm + GH2_OFF, feat, tid);

    float* tgtb = sm + TGTB_OFF;
    for (int idx = tid; idx < 32*128; idx += NTHREADS) {
        int r = idx >> 7, c = idx & 127;
        tgtb[idx] = feat[((r >> 1)*3 + (r & 1))*128 + c];
    }
    __syncthreads();
    float* Wq = sm + WQ_OFF;
    gemm_direct<128,128,4,2,false,128>(g_WT_att2, att_w2_b, tgtb, 128, Wq, 128, tid);
    float* Wp = sm + WP_OFF;
    gemm_direct<128,128,2,2,false,128>(g_WT_att1, att_w1_b, feat + 256, 384, Wp, 128, tid);

    float* scb = sm + SC_OFF;
    {
        int pk = tid >> 3, sub = tid & 7;
        int p = pk >> 1, k = pk & 1;
        float s = 0.f;
        for (int j = sub; j < 128; j += 8)
            s += Wp[p*128 + j] * Wq[(2*p + k)*128 + j];
        s += __shfl_down_sync(0xffffffffu, s, 4, 8);
        s += __shfl_down_sync(0xffffffffu, s, 2, 8);
        s += __shfl_down_sync(0xffffffffu, s, 1, 8);
        if (sub == 0) scb[pk] = s;
    }
    __syncthreads();
    if (tid < PAIRS) {
        float s0 = scb[2*tid], s1 = scb[2*tid + 1];
        float m = fmaxf(s0, s1);
        float e0 = __expf(s0 - m), e1 = __expf(s1 - m);
        float inv = 1.f / (e0 + e1);
        scb[2*tid]     = e0 * inv;
        scb[2*tid + 1] = e1 * inv;
    }
    __syncthreads();
    float* outb = sm + OUTB_OFF;
    for (int idx = tid; idx < PAIRS*128; idx += NTHREADS) {
        int p = idx >> 7, c = idx & 127;
        outb[idx] = feat[(p*3 + 2)*128 + c]
                  + scb[2*p]     * Wq[(2*p)*128 + c]
                  + scb[2*p + 1] * Wq[(2*p + 1)*128 + c];
    }
    __syncthreads();

    float* hb = sm + HB_OFF;
    float* sf = sm + SF_OFF;
    gemm_direct<64,128,2,1,true,64>(g_WT_m1, att_m1_b, outb, 128, hb, 64, tid);
    gemm_direct<64,64,2,1,false,64>(g_WT_m2, att_m2_b, hb, 64, sf, 64, tid);

    float* xb  = sm + XB_OFF;
    float* h1b = sm + H1_OFF;
    float* h2b = sm + H2_OFF;
    for (int idx = tid; idx < PAIRS*76; idx += NTHREADS) {
        int p = idx / 76, c = idx - p*76;
        float v;
        if (c < 64) v = sf[p*64 + c];
        else        v = (__ldg(&cat_feat[g0 + p]) == (c - 64)) ? 1.f : 0.f;
        xb[idx] = v;
    }
    __syncthreads();
    for (int idx = tid; idx < PAIRS*76; idx += NTHREADS) {
        int p = idx / 76, c = idx - p*76;
        const float* w = mlp_w1 + c*76;
        const float* x = xb + p*76;
        float s = __ldg(&mlp_b1[c]);
#pragma unroll 4
        for (int k = 0; k < 76; k++) s += x[k] * __ldg(&w[k]);
        h1b[idx] = fmaxf(s, 0.f);
    }
    __syncthreads();
    for (int idx = tid; idx < PAIRS*64; idx += NTHREADS) {
        int p = idx >> 6, c = idx & 63;
        const float* w = mlp_w2 + c*76;
        const float* x = h1b + p*76;
        float s = __ldg(&mlp_b2[c]);
#pragma unroll 4
        for (int k = 0; k < 76; k++) s += x[k] * __ldg(&w[k]);
        h2b[idx] = fmaxf(s, 0.f);
    }
    __syncthreads();
    if (tid < PAIRS) {
        float z = __ldg(&mlp_b3[0]);
        const float* x = h2b + tid*64;
#pragma unroll 4
        for (int k = 0; k < 64; k++) z += x[k] * __ldg(&mlp_w3[k]);
        out[g0 + tid] = 1.f / (1.f + __expf(-z));
    }
}

extern "C" void kernel_launch(void* const* d_in, const int* in_sizes, int n_in,
                              void* d_out, int out_size)
{
    const int*   node_idx      = (const int*)  d_in[0];
    const int*   edge_idx      = (const int*)  d_in[1];
    const int*   cat_feat      = (const int*)  d_in[2];
    const float* t_records     = (const float*)d_in[3];
    const float* edge_identify = (const float*)d_in[4];
    const float* node_embed    = (const float*)d_in[6];
    const float* edge_embed    = (const float*)d_in[7];
    const float* basis_freq    = (const float*)d_in[8];
    const float* phase         = (const float*)d_in[9];
    const float* lin_event_w   = (const float*)d_in[10];
    const float* lin_event_b   = (const float*)d_in[11];
    const float* gcn_w1        = (const float*)d_in[12];
    const float* gcn_b1        = (const float*)d_in[13];
    const float* gcn_w2        = (const float*)d_in[14];
    const float* gcn_b2        = (const float*)d_in[15];
    const float* att_w1_w      = (const float*)d_in[16];
    const float* att_w1_b      = (const float*)d_in[17];
    const float* att_w2_w      = (const float*)d_in[18];
    const float* att_w2_b      = (const float*)d_in[19];
    const float* att_m1_w      = (const float*)d_in[20];
    const float* att_m1_b      = (const float*)d_in[21];
    const float* att_m2_w      = (const float*)d_in[22];
    const float* att_m2_b      = (const float*)d_in[23];
    const float* mlp_w1        = (const float*)d_in[24];
    const float* mlp_b1        = (const float*)d_in[25];
    const float* mlp_w2        = (const float*)d_in[26];
    const float* mlp_b2        = (const float*)d_in[27];
    const float* mlp_w3        = (const float*)d_in[28];
    const float* mlp_b3        = (const float*)d_in[29];
    float* outp = (float*)d_out;

    cudaFuncSetAttribute(fused_kernel,
                         cudaFuncAttributeMaxDynamicSharedMemorySize, SMEM_BYTES);
    cudaFuncSetAttribute(event_mma_kernel,
                         cudaFuncAttributeMaxDynamicSharedMemorySize, EV_SMEM_BYTES);

    prep_kernel<<<128, 256>>>(lin_event_w, gcn_w1, gcn_w2,
                              att_w1_w, att_w2_w, att_m1_w, att_m2_w);
    dim3 egrid(768, 2, 1);
    event_mma_kernel<<<egrid, EK_THREADS, EV_SMEM_BYTES>>>(
        edge_idx, edge_embed, edge_identify, t_records, basis_freq, phase, lin_event_b);
    fused_kernel<<<NBLK, NTHREADS, SMEM_BYTES>>>(
        node_idx, cat_feat, node_embed,
        gcn_b1, gcn_b2,
        att_w1_b, att_w2_b, att_m1_b, att_m2_b,
        mlp_w1, mlp_b1, mlp_w2, mlp_b2, mlp_w3, mlp_b3,
        outp);
}

// round 9
// speedup vs baseline: 1.1952x; 1.1952x over previous
#include <cuda_runtime.h>
#include <math.h>
#include <stdint.h>

#define NTHREADS 256
#define PAIRS    16
#define ROWS     48
#define NBLK     2048

typedef unsigned long long ull;

// fused-kernel smem layout (floats): 18816 floats -> 3 blocks/SM
#define EVT_OFF   0
#define FEAT_OFF  8448
#define ABUF_OFF  14592
#define SMEM_FLOATS 18816
#define SMEM_BYTES (SMEM_FLOATS*4)
#define GH1_OFF   (EVT_OFF + 0)
#define GH2_OFF   (EVT_OFF + 3072)
#define TGTB_OFF  (EVT_OFF + 0)
#define WQ_OFF    (EVT_OFF + 4096)
#define WP_OFF    (EVT_OFF + 0)
#define OUTB_OFF  (ABUF_OFF + 0)
#define SC_OFF    (ABUF_OFF + 2048)
#define HB_OFF    (FEAT_OFF + 0)
#define SF_OFF    (FEAT_OFF + 1024)
#define XB_OFF    (FEAT_OFF + 2048)
#define H1_OFF    (FEAT_OFF + 3264)
#define H2_OFF    (FEAT_OFF + 4480)

__device__ __forceinline__ ull pack2(float lo, float hi) {
    ull r; asm("mov.b64 %0, {%1, %2};" : "=l"(r) : "f"(lo), "f"(hi)); return r;
}
__device__ __forceinline__ void unpack2(ull v, float& lo, float& hi) {
    asm("mov.b64 {%0, %1}, %2;" : "=f"(lo), "=f"(hi) : "l"(v));
}
__device__ __forceinline__ void fma2(ull& d, ull a, ull b) {
    asm("fma.rn.f32x2 %0, %1, %2, %0;" : "+l"(d) : "l"(a), "l"(b));
}
__device__ __forceinline__ float fsel4(float4 v, int kk) {
    return (kk==0)?v.x:(kk==1)?v.y:(kk==2)?v.z:v.w;
}

// ---------------------------------------------------------------------------
// Pre-transposed / padded weights ([k][o] layout, zero padded).
// Each array has ONE EXTRA k-row so the k+1 prefetch never needs a guard
// (pad rows are zero-initialized device globals, loaded but never used).
// ---------------------------------------------------------------------------
__device__ __align__(16) float g_WT_event[353*192];
__device__ __align__(16) float g_WT_gcn1 [177*64];
__device__ __align__(16) float g_WT_gcn2 [ 65*64];
__device__ __align__(16) float g_WT_att1 [129*128];
__device__ __align__(16) float g_WT_att2 [129*128];
__device__ __align__(16) float g_WT_m1   [129*64];
__device__ __align__(16) float g_WT_m2   [ 65*64];

__global__ void prep_kernel(const float* __restrict__ ew,
                            const float* __restrict__ g1,
                            const float* __restrict__ g2,
                            const float* __restrict__ a1,
                            const float* __restrict__ a2,
                            const float* __restrict__ m1,
                            const float* __restrict__ m2)
{
    int t0 = blockIdx.x*blockDim.x + threadIdx.x;
    int stride = gridDim.x*blockDim.x;
    for (int i = t0; i < 352*192; i += stride) {
        int k = i/192, o = i%192;
        g_WT_event[i] = (k < 347 && o < 172) ? ew[o*347 + k] : 0.f;
    }
    for (int i = t0; i < 176*64; i += stride) {
        int k = i/64, o = i%64;
        g_WT_gcn1[i] = (k < 172) ? g1[o*172 + k] : 0.f;
    }
    for (int i = t0; i < 64*64; i += stride) {
        int k = i/64, o = i%64;
        g_WT_gcn2[i] = g2[o*64 + k];
        g_WT_m2[i]   = m2[o*64 + k];
    }
    for (int i = t0; i < 128*128; i += stride) {
        int k = i/128, o = i%128;
        g_WT_att1[i] = a1[o*128 + k];
        g_WT_att2[i] = a2[o*128 + k];
    }
    for (int i = t0; i < 128*64; i += stride) {
        int k = i/64, o = i%64;
        g_WT_m1[i] = m1[o*128 + k];
    }
}

// ---------------------------------------------------------------------------
// Direct GEMM with double-buffered weight prefetch.
// 8 warps; thread (ty,tx): rows [ty*RT,..+RT), cols {g*64+2tx,+1}, g<P.
// ---------------------------------------------------------------------------
template<int NS, int K, int RT, int P, bool RELU, int NREAL>
__device__ __forceinline__ void gemm_direct(
    const float* __restrict__ Wg, const float* __restrict__ bias,
    const float* __restrict__ A, int sa,
    float* __restrict__ C, int sc, int tid)
{
    const int ty = tid >> 5, tx = tid & 31;
    ull acc[RT][P];
#pragma unroll
    for (int i = 0; i < RT; i++)
#pragma unroll
        for (int g = 0; g < P; g++) acc[i][g] = 0ull;

    const float* wq   = Wg + 2*tx;
    const float* arow = A + ty*RT*sa;

    ull wbuf[2][P];
#pragma unroll
    for (int g = 0; g < P; g++)
        wbuf[0][g] = __ldg(reinterpret_cast<const ull*>(wq + g*64));

#pragma unroll 1
    for (int k4 = 0; k4 < K; k4 += 4) {
        float4 av[RT];
#pragma unroll
        for (int i = 0; i < RT; i++)
            av[i] = *reinterpret_cast<const float4*>(arow + i*sa + k4);
#pragma unroll
        for (int kk = 0; kk < 4; kk++) {
#pragma unroll
            for (int g = 0; g < P; g++)
                wbuf[(kk+1)&1][g] =
                    __ldg(reinterpret_cast<const ull*>(wq + (k4+kk+1)*NS + g*64));
#pragma unroll
            for (int i = 0; i < RT; i++) {
                float a = fsel4(av[i], kk);
                ull ad = pack2(a, a);
#pragma unroll
                for (int g = 0; g < P; g++) fma2(acc[i][g], ad, wbuf[kk&1][g]);
            }
        }
    }
#pragma unroll
    for (int i = 0; i < RT; i++)
#pragma unroll
        for (int g = 0; g < P; g++) {
            int col = g*64 + 2*tx;
            float x, y; unpack2(acc[i][g], x, y);
            int row = ty*RT + i;
            if (col < NREAL) {
                float v = x + __ldg(&bias[col]);
                if (RELU) v = fmaxf(v, 0.f);
                C[row*sc + col] = v;
            }
            if (col + 1 < NREAL) {
                float v = y + __ldg(&bias[col+1]);
                if (RELU) v = fmaxf(v, 0.f);
                C[row*sc + col + 1] = v;
            }
        }
    __syncthreads();
}

// ---------------------------------------------------------------------------
// Event generator (one 48x44 chunk of event_f)
// ---------------------------------------------------------------------------
struct EventGen {
    const int*   edge_idx;
    const float* edge_embed;
    const float* edge_identify;
    const float* t_records;
    const float* basis_freq;
    const float* phase;
    int g0;
    __device__ __forceinline__ void operator()(float* Abuf, int kc, int tid) const {
        for (int idx = tid; idx < ROWS*44; idx += NTHREADS) {
            int r = idx / 44, cc = idx - r*44;
            int c = kc + cc;
            int p = r / 3, l = r - p*3;
            int g = g0 + p;
            float v = 0.f;
            if (c < 172) {
                int e = __ldg(&edge_idx[g*3 + l]);
                v = __ldg(&edge_embed[(long)e*172 + c]);
            } else if (c < 175) {
                v = __ldg(&edge_identify[(g*3 + l)*3 + (c - 172)]);
            } else if (c < 347) {
                int d = c - 175;
                float dt = __ldg(&t_records[g*3 + 2]) - __ldg(&t_records[g*3 + l]);
                v = __cosf(dt * __ldg(&basis_freq[d]) + __ldg(&phase[d]));
            }
            Abuf[idx] = v;
        }
    }
};

// ---------------------------------------------------------------------------
// Event GEMM: double-buffered gen + double-buffered weight prefetch.
// K=352 (8 chunks of 44), N stride 192, real 172, RT=6, P=3.
// ---------------------------------------------------------------------------
__device__ __forceinline__ void gemm_event(
    const float* __restrict__ bias,
    float* __restrict__ Abuf, const EventGen& gen,
    float* __restrict__ C, int tid)
{
    const int ty = tid >> 5, tx = tid & 31;
    ull acc[6][3];
#pragma unroll
    for (int i = 0; i < 6; i++)
#pragma unroll
        for (int g = 0; g < 3; g++) acc[i][g] = 0ull;

    const float* wqg = g_WT_event + 2*tx;
    ull wbuf[2][3];
#pragma unroll
    for (int g = 0; g < 3; g++)
        wbuf[0][g] = __ldg(reinterpret_cast<const ull*>(wqg + g*64));

    gen(Abuf, 0, tid);
    __syncthreads();
#pragma unroll 1
    for (int kc = 0; kc < 352; kc += 44) {
        int buf = (kc / 44) & 1;
        const float* cur = Abuf + buf*2112;
        if (kc + 44 < 352) gen(Abuf + (buf^1)*2112, kc + 44, tid);
        const float* arow = cur + ty*6*44;
#pragma unroll 1
        for (int k4 = 0; k4 < 44; k4 += 4) {
            float4 av[6];
#pragma unroll
            for (int i = 0; i < 6; i++)
                av[i] = *reinterpret_cast<const float4*>(arow + i*44 + k4);
#pragma unroll
            for (int kk = 0; kk < 4; kk++) {
#pragma unroll
                for (int g = 0; g < 3; g++)
                    wbuf[(kk+1)&1][g] = __ldg(reinterpret_cast<const ull*>(
                        wqg + (kc + k4 + kk + 1)*192 + g*64));
#pragma unroll
                for (int i = 0; i < 6; i++) {
                    float a = fsel4(av[i], kk);
                    ull ad = pack2(a, a);
#pragma unroll
                    for (int g = 0; g < 3; g++) fma2(acc[i][g], ad, wbuf[kk&1][g]);
                }
            }
        }
        __syncthreads();
    }
#pragma unroll
    for (int i = 0; i < 6; i++)
#pragma unroll
        for (int g = 0; g < 3; g++) {
            int col = g*64 + 2*tx;
            float x, y; unpack2(acc[i][g], x, y);
            int row = ty*6 + i;
            if (col < 172)     C[row*176 + col]     = x + __ldg(&bias[col]);
            if (col + 1 < 172) C[row*176 + col + 1] = y + __ldg(&bias[col+1]);
        }
    __syncthreads();
}

// ---------------------------------------------------------------------------
// Dual gine: one gen pass produces both inputs; one GEMM loop accumulates
// both against shared gcn1 weight loads (double-buffered prefetch).
// ---------------------------------------------------------------------------
struct GineDualGen {
    const int*   node_idx;
    const float* node_embed;
    const float* evt;   // smem, pitch 176
    int g0;
    __device__ __forceinline__ void operator()(float* Abuf, int kc, int tid) const {
        for (int idx = tid; idx < ROWS*44; idx += NTHREADS) {
            int r = idx / 44, cc = idx - r*44;
            int c = kc + cc;
            int p = r / 3, l = r - p*3;
            int g = g0 + p;
            float v1 = 0.f, v2 = 0.f;
            if (c < 172) {
                int ns = __ldg(&node_idx[g*6 + 2*l]);
                int nt = __ldg(&node_idx[g*6 + 2*l + 1]);
                float s = __ldg(&node_embed[(long)ns*172 + c]);
                float t = __ldg(&node_embed[(long)nt*172 + c]);
                float e = evt[r*176 + c];
                v1 = s + fmaxf(t + e, 0.f);
                v2 = t + fmaxf(s + e, 0.f);
            }
            Abuf[idx]        = v1;
            Abuf[2112 + idx] = v2;
        }
    }
};

__device__ __forceinline__ void gemm_gine_dual(
    const float* __restrict__ bias,
    float* __restrict__ Abuf, const GineDualGen& gen,
    float* __restrict__ C1, float* __restrict__ C2, int tid)
{
    const int ty = tid >> 5, tx = tid & 31;
    ull acc1[6], acc2[6];
#pragma unroll
    for (int i = 0; i < 6; i++) { acc1[i] = 0ull; acc2[i] = 0ull; }

    const float* wqg = g_WT_gcn1 + 2*tx;
    ull wb[2];
    wb[0] = __ldg(reinterpret_cast<const ull*>(wqg));

#pragma unroll 1
    for (int kc = 0; kc < 176; kc += 44) {
        __syncthreads();
        gen(Abuf, kc, tid);
        __syncthreads();
        const float* a1row = Abuf + ty*6*44;
        const float* a2row = Abuf + 2112 + ty*6*44;
#pragma unroll 1
        for (int k4 = 0; k4 < 44; k4 += 4) {
#pragma unroll
            for (int kk = 0; kk < 4; kk++) {
                wb[(kk+1)&1] = __ldg(reinterpret_cast<const ull*>(
                    wqg + (kc + k4 + kk + 1)*64));
#pragma unroll
                for (int i = 0; i < 6; i++) {
                    float a1 = a1row[i*44 + k4 + kk];
                    float a2 = a2row[i*44 + k4 + kk];
                    fma2(acc1[i], pack2(a1, a1), wb[kk&1]);
                    fma2(acc2[i], pack2(a2, a2), wb[kk&1]);
                }
            }
        }
    }
    int col = 2*tx;
    float b0 = __ldg(&bias[col]), b1 = __ldg(&bias[col+1]);
#pragma unroll
    for (int i = 0; i < 6; i++) {
        int row = ty*6 + i;
        float x, y;
        unpack2(acc1[i], x, y);
        C1[row*64 + col]     = fmaxf(x + b0, 0.f);
        C1[row*64 + col + 1] = fmaxf(y + b1, 0.f);
        unpack2(acc2[i], x, y);
        C2[row*64 + col]     = fmaxf(x + b0, 0.f);
        C2[row*64 + col + 1] = fmaxf(y + b1, 0.f);
    }
    __syncthreads();
}

// Dual gcn2: H1,H2 (pitch 64) -> feat[:,0:64] & feat[:,64:128], shared weights.
__device__ __forceinline__ void gemm_gcn2_dual(
    const float* __restrict__ bias,
    const float* __restrict__ H1, const float* __restrict__ H2,
    float* __restrict__ feat, int tid)
{
    const int ty = tid >> 5, tx = tid & 31;
    ull acc1[6], acc2[6];
#pragma unroll
    for (int i = 0; i < 6; i++) { acc1[i] = 0ull; acc2[i] = 0ull; }
    const float* wqg = g_WT_gcn2 + 2*tx;
    ull wb[2];
    wb[0] = __ldg(reinterpret_cast<const ull*>(wqg));
#pragma unroll 1
    for (int k4 = 0; k4 < 64; k4 += 4) {
        float4 a1v[6], a2v[6];
#pragma unroll
        for (int i = 0; i < 6; i++) {
            a1v[i] = *reinterpret_cast<const float4*>(H1 + (ty*6+i)*64 + k4);
            a2v[i] = *reinterpret_cast<const float4*>(H2 + (ty*6+i)*64 + k4);
        }
#pragma unroll
        for (int kk = 0; kk < 4; kk++) {
            wb[(kk+1)&1] = __ldg(reinterpret_cast<const ull*>(wqg + (k4+kk+1)*64));
#pragma unroll
            for (int i = 0; i < 6; i++) {
                float a1 = fsel4(a1v[i], kk);
                float a2 = fsel4(a2v[i], kk);
                fma2(acc1[i], pack2(a1, a1), wb[kk&1]);
                fma2(acc2[i], pack2(a2, a2), wb[kk&1]);
            }
        }
    }
    int col = 2*tx;
    float b0 = __ldg(&bias[col]), b1 = __ldg(&bias[col+1]);
#pragma unroll
    for (int i = 0; i < 6; i++) {
        int row = ty*6 + i;
        float x, y;
        unpack2(acc1[i], x, y);
        feat[row*128 + col]      = x + b0;
        feat[row*128 + col + 1]  = y + b1;
        unpack2(acc2[i], x, y);
        feat[row*128 + 64 + col]     = x + b0;
        feat[row*128 + 64 + col + 1] = y + b1;
    }
    __syncthreads();
}

// ---------------------------------------------------------------------------
// Fused main kernel: one block (8 warps) handles 16 (b,w) pairs end-to-end.
// ---------------------------------------------------------------------------
__global__ void __launch_bounds__(NTHREADS, 3)
fused_kernel(const int*   __restrict__ node_idx,
             const int*   __restrict__ edge_idx,
             const int*   __restrict__ cat_feat,
             const float* __restrict__ t_records,
             const float* __restrict__ edge_identify,
             const float* __restrict__ node_embed,
             const float* __restrict__ edge_embed,
             const float* __restrict__ basis_freq,
             const float* __restrict__ phase,
             const float* __restrict__ lin_event_b,
             const float* __restrict__ gcn_b1,
             const float* __restrict__ gcn_b2,
             const float* __restrict__ att_w1_b,
             const float* __restrict__ att_w2_b,
             const float* __restrict__ att_m1_b,
             const float* __restrict__ att_m2_b,
             const float* __restrict__ mlp_w1,
             const float* __restrict__ mlp_b1,
             const float* __restrict__ mlp_w2,
             const float* __restrict__ mlp_b2,
             const float* __restrict__ mlp_w3,
             const float* __restrict__ mlp_b3,
             float*       __restrict__ out)
{
    extern __shared__ float sm[];
    const int tid = threadIdx.x;
    const int g0  = blockIdx.x * PAIRS;

    float* evt  = sm + EVT_OFF;
    float* feat = sm + FEAT_OFF;
    float* Abuf = sm + ABUF_OFF;

    // ---- Phase 1: event linear (double-buffered gen + weight prefetch) ----
    EventGen eg{edge_idx, edge_embed, edge_identify, t_records, basis_freq, phase, g0};
    gemm_event(lin_event_b, Abuf, eg, evt, tid);

    // ---- Phase 2: dual gine -> GH1/GH2 ----
    GineDualGen gg{node_idx, node_embed, evt, g0};
    gemm_gine_dual(gcn_b1, Abuf, gg, sm + GH1_OFF, sm + GH2_OFF, tid);

    // ---- Phase 3: dual gcn2 -> feat ----
    gemm_gcn2_dual(gcn_b2, sm + GH1_OFF, sm + GH2_OFF, feat, tid);

    // ---- Phase 4: attention ----
    float* tgtb = sm + TGTB_OFF;
    for (int idx = tid; idx < 32*128; idx += NTHREADS) {
        int r = idx >> 7, c = idx & 127;
        tgtb[idx] = feat[((r >> 1)*3 + (r & 1))*128 + c];
    }
    __syncthreads();
    float* Wq = sm + WQ_OFF;
    gemm_direct<128,128,4,2,false,128>(g_WT_att2, att_w2_b, tgtb, 128, Wq, 128, tid);
    float* Wp = sm + WP_OFF;   // overwrites tgtb (dead)
    gemm_direct<128,128,2,2,false,128>(g_WT_att1, att_w1_b, feat + 256, 384, Wp, 128, tid);

    float* scb = sm + SC_OFF;
    {
        int pk = tid >> 3, sub = tid & 7;
        int p = pk >> 1, k = pk & 1;
        float s = 0.f;
        for (int j = sub; j < 128; j += 8)
            s += Wp[p*128 + j] * Wq[(2*p + k)*128 + j];
        s += __shfl_down_sync(0xffffffffu, s, 4, 8);
        s += __shfl_down_sync(0xffffffffu, s, 2, 8);
        s += __shfl_down_sync(0xffffffffu, s, 1, 8);
        if (sub == 0) scb[pk] = s;
    }
    __syncthreads();
    if (tid < PAIRS) {
        float s0 = scb[2*tid], s1 = scb[2*tid + 1];
        float m = fmaxf(s0, s1);
        float e0 = __expf(s0 - m), e1 = __expf(s1 - m);
        float inv = 1.f / (e0 + e1);
        scb[2*tid]     = e0 * inv;
        scb[2*tid + 1] = e1 * inv;
    }
    __syncthreads();
    float* outb = sm + OUTB_OFF;
    for (int idx = tid; idx < PAIRS*128; idx += NTHREADS) {
        int p = idx >> 7, c = idx & 127;
        outb[idx] = feat[(p*3 + 2)*128 + c]
                  + scb[2*p]     * Wq[(2*p)*128 + c]
                  + scb[2*p + 1] * Wq[(2*p + 1)*128 + c];
    }
    __syncthreads();

    float* hb = sm + HB_OFF;
    float* sf = sm + SF_OFF;
    gemm_direct<64,128,2,1,true,64>(g_WT_m1, att_m1_b, outb, 128, hb, 64, tid);
    gemm_direct<64,64,2,1,false,64>(g_WT_m2, att_m2_b, hb, 64, sf, 64, tid);

    // ---- Phase 5: MLP tail ----
    float* xb  = sm + XB_OFF;
    float* h1b = sm + H1_OFF;
    float* h2b = sm + H2_OFF;
    for (int idx = tid; idx < PAIRS*76; idx += NTHREADS) {
        int p = idx / 76, c = idx - p*76;
        float v;
        if (c < 64) v = sf[p*64 + c];
        else        v = (__ldg(&cat_feat[g0 + p]) == (c - 64)) ? 1.f : 0.f;
        xb[idx] = v;
    }
    __syncthreads();
    for (int idx = tid; idx < PAIRS*76; idx += NTHREADS) {
        int p = idx / 76, c = idx - p*76;
        const float* w = mlp_w1 + c*76;
        const float* x = xb + p*76;
        float s = __ldg(&mlp_b1[c]);
#pragma unroll 4
        for (int k = 0; k < 76; k++) s += x[k] * __ldg(&w[k]);
        h1b[idx] = fmaxf(s, 0.f);
    }
    __syncthreads();
    for (int idx = tid; idx < PAIRS*64; idx += NTHREADS) {
        int p = idx >> 6, c = idx & 63;
        const float* w = mlp_w2 + c*76;
        const float* x = h1b + p*76;
        float s = __ldg(&mlp_b2[c]);
#pragma unroll 4
        for (int k = 0; k < 76; k++) s += x[k] * __ldg(&w[k]);
        h2b[idx] = fmaxf(s, 0.f);
    }
    __syncthreads();
    if (tid < PAIRS) {
        float z = __ldg(&mlp_b3[0]);
        const float* x = h2b + tid*64;
#pragma unroll 4
        for (int k = 0; k < 64; k++) z += x[k] * __ldg(&mlp_w3[k]);
        out[g0 + tid] = 1.f / (1.f + __expf(-z));
    }
}

// ---------------------------------------------------------------------------
// Launch
// ---------------------------------------------------------------------------
extern "C" void kernel_launch(void* const* d_in, const int* in_sizes, int n_in,
                              void* d_out, int out_size)
{
    const int*   node_idx      = (const int*)  d_in[0];
    const int*   edge_idx      = (const int*)  d_in[1];
    const int*   cat_feat      = (const int*)  d_in[2];
    const float* t_records     = (const float*)d_in[3];
    const float* edge_identify = (const float*)d_in[4];
    // d_in[5] = cut_time_l (unused by reference)
    const float* node_embed    = (const float*)d_in[6];
    const float* edge_embed    = (const float*)d_in[7];
    const float* basis_freq    = (const float*)d_in[8];
    const float* phase         = (const float*)d_in[9];
    const float* lin_event_w   = (const float*)d_in[10];
    const float* lin_event_b   = (const float*)d_in[11];
    const float* gcn_w1        = (const float*)d_in[12];
    const float* gcn_b1        = (const float*)d_in[13];
    const float* gcn_w2        = (const float*)d_in[14];
    const float* gcn_b2        = (const float*)d_in[15];
    const float* att_w1_w      = (const float*)d_in[16];
    const float* att_w1_b      = (const float*)d_in[17];
    const float* att_w2_w      = (const float*)d_in[18];
    const float* att_w2_b      = (const float*)d_in[19];
    const float* att_m1_w      = (const float*)d_in[20];
    const float* att_m1_b      = (const float*)d_in[21];
    const float* att_m2_w      = (const float*)d_in[22];
    const float* att_m2_b      = (const float*)d_in[23];
    const float* mlp_w1        = (const float*)d_in[24];
    const float* mlp_b1        = (const float*)d_in[25];
    const float* mlp_w2        = (const float*)d_in[26];
    const float* mlp_b2        = (const float*)d_in[27];
    const float* mlp_w3        = (const float*)d_in[28];
    const float* mlp_b3        = (const float*)d_in[29];
    float* outp = (float*)d_out;

    cudaFuncSetAttribute(fused_kernel,
                         cudaFuncAttributeMaxDynamicSharedMemorySize, SMEM_BYTES);

    prep_kernel<<<128, 256>>>(lin_event_w, gcn_w1, gcn_w2,
                              att_w1_w, att_w2_w, att_m1_w, att_m2_w);

    fused_kernel<<<NBLK, NTHREADS, SMEM_BYTES>>>(
        node_idx, edge_idx, cat_feat, t_records, edge_identify,
        node_embed, edge_embed, basis_freq, phase,
        lin_event_b, gcn_b1, gcn_b2,
        att_w1_b, att_w2_b, att_m1_b, att_m2_b,
        mlp_w1, mlp_b1, mlp_w2, mlp_b2, mlp_w3, mlp_b3,
        outp);
}

// round 10
// speedup vs baseline: 1.8241x; 1.5263x over previous
#include <cuda_runtime.h>
#include <math.h>
#include <stdint.h>

#define NTHREADS 256
#define PAIRS    16
#define ROWS     48
#define NBLK     2048

typedef unsigned long long ull;

// fused-kernel smem layout (floats): 18816 floats -> 3 blocks/SM
#define EVT_OFF   0
#define FEAT_OFF  8448
#define ABUF_OFF  14592
#define SMEM_FLOATS 18816
#define SMEM_BYTES (SMEM_FLOATS*4)
#define GH1_OFF   (EVT_OFF + 0)
#define GH2_OFF   (EVT_OFF + 3072)
#define TGTB_OFF  (EVT_OFF + 0)
#define WQ_OFF    (EVT_OFF + 4096)
#define WP_OFF    (EVT_OFF + 0)
#define OUTB_OFF  (ABUF_OFF + 0)
#define SC_OFF    (ABUF_OFF + 2048)
#define HB_OFF    (FEAT_OFF + 0)
#define SF_OFF    (FEAT_OFF + 1024)
#define XB_OFF    (FEAT_OFF + 2048)
#define H1_OFF    (FEAT_OFF + 3264)
#define H2_OFF    (FEAT_OFF + 4480)

__device__ __forceinline__ ull pack2(float lo, float hi) {
    ull r; asm("mov.b64 %0, {%1, %2};" : "=l"(r) : "f"(lo), "f"(hi)); return r;
}
__device__ __forceinline__ void unpack2(ull v, float& lo, float& hi) {
    asm("mov.b64 {%0, %1}, %2;" : "=f"(lo), "=f"(hi) : "l"(v));
}
__device__ __forceinline__ void fma2(ull& d, ull a, ull b) {
    asm("fma.rn.f32x2 %0, %1, %2, %0;" : "+l"(d) : "l"(a), "l"(b));
}
__device__ __forceinline__ float fsel4(float4 v, int kk) {
    return (kk==0)?v.x:(kk==1)?v.y:(kk==2)?v.z:v.w;
}

// ---------------------------------------------------------------------------
// Pre-transposed / padded weights ([k][o] layout, zero padded)
// ---------------------------------------------------------------------------
__device__ __align__(16) float g_WT_event[352*192];
__device__ __align__(16) float g_WT_gcn1 [176*64];
__device__ __align__(16) float g_WT_gcn2 [ 64*64];
__device__ __align__(16) float g_WT_att1 [128*128];
__device__ __align__(16) float g_WT_att2 [128*128];
__device__ __align__(16) float g_WT_m1   [128*64];
__device__ __align__(16) float g_WT_m2   [ 64*64];
__device__ __align__(16) float g_WT_mlp1 [76*128];
__device__ __align__(16) float g_WT_mlp2 [76*64];
__device__ __align__(16) float g_ct2     [192];     // sum_d>=1 cos(phase_d)*W[:,175+d]

__global__ void prep_kernel(const float* __restrict__ ew,
                            const float* __restrict__ g1,
                            const float* __restrict__ g2,
                            const float* __restrict__ a1,
                            const float* __restrict__ a2,
                            const float* __restrict__ m1,
                            const float* __restrict__ m2,
                            const float* __restrict__ w1,
                            const float* __restrict__ w2,
                            const float* __restrict__ ph)
{
    int t0 = blockIdx.x*blockDim.x + threadIdx.x;
    int stride = gridDim.x*blockDim.x;
    for (int i = t0; i < 352*192; i += stride) {
        int k = i/192, o = i%192;
        g_WT_event[i] = (k < 347 && o < 172) ? ew[o*347 + k] : 0.f;
    }
    for (int i = t0; i < 176*64; i += stride) {
        int k = i/64, o = i%64;
        g_WT_gcn1[i] = (k < 172) ? g1[o*172 + k] : 0.f;
    }
    for (int i = t0; i < 64*64; i += stride) {
        int k = i/64, o = i%64;
        g_WT_gcn2[i] = g2[o*64 + k];
        g_WT_m2[i]   = m2[o*64 + k];
    }
    for (int i = t0; i < 128*128; i += stride) {
        int k = i/128, o = i%128;
        g_WT_att1[i] = a1[o*128 + k];
        g_WT_att2[i] = a2[o*128 + k];
    }
    for (int i = t0; i < 128*64; i += stride) {
        int k = i/64, o = i%64;
        g_WT_m1[i] = m1[o*128 + k];
    }
    for (int i = t0; i < 76*128; i += stride) {
        int k = i/128, o = i%128;
        g_WT_mlp1[i] = (o < 76) ? w1[o*76 + k] : 0.f;
    }
    for (int i = t0; i < 76*64; i += stride) {
        int k = i/64, o = i%64;
        g_WT_mlp2[i] = w2[o*76 + k];
    }
    // c_t2[o] = sum_{d=1}^{171} cos(phase[d]) * W[o, 175+d]
    for (int o = t0; o < 192; o += stride) {
        float s = 0.f;
        if (o < 172) {
            for (int d = 1; d < 172; d++)
                s += cosf(ph[d]) * ew[o*347 + 175 + d];
        }
        g_ct2[o] = s;
    }
}

// ---------------------------------------------------------------------------
// Direct GEMM (R6 style: batch 4 k's of weights up-front). 8 warps.
// Thread (ty,tx): rows [ty*RT,..+RT), cols {g*64+2tx,+1}, g<P.
// ---------------------------------------------------------------------------
template<int NS, int K, int RT, int P, bool RELU, int NREAL>
__device__ __forceinline__ void gemm_direct(
    const float* __restrict__ Wg, const float* __restrict__ bias,
    const float* __restrict__ A, int sa,
    float* __restrict__ C, int sc, int tid)
{
    const int ty = tid >> 5, tx = tid & 31;
    ull acc[RT][P];
#pragma unroll
    for (int i = 0; i < RT; i++)
#pragma unroll
        for (int g = 0; g < P; g++) acc[i][g] = 0ull;
    const float* wq   = Wg + 2*tx;
    const float* arow = A + ty*RT*sa;
#pragma unroll 1
    for (int k4 = 0; k4 < K; k4 += 4) {
        ull w[4][P];
#pragma unroll
        for (int kk = 0; kk < 4; kk++)
#pragma unroll
            for (int g = 0; g < P; g++)
                w[kk][g] = __ldg(reinterpret_cast<const ull*>(wq + (k4+kk)*NS + g*64));
        float4 av[RT];
#pragma unroll
        for (int i = 0; i < RT; i++)
            av[i] = *reinterpret_cast<const float4*>(arow + i*sa + k4);
#pragma unroll
        for (int kk = 0; kk < 4; kk++)
#pragma unroll
            for (int i = 0; i < RT; i++) {
                float a = fsel4(av[i], kk);
                ull ad = pack2(a, a);
#pragma unroll
                for (int g = 0; g < P; g++) fma2(acc[i][g], ad, w[kk][g]);
            }
    }
#pragma unroll
    for (int i = 0; i < RT; i++)
#pragma unroll
        for (int g = 0; g < P; g++) {
            int col = g*64 + 2*tx;
            float x, y; unpack2(acc[i][g], x, y);
            int row = ty*RT + i;
            if (col < NREAL) {
                float v = x + __ldg(&bias[col]);
                if (RELU) v = fmaxf(v, 0.f);
                C[row*sc + col] = v;
            }
            if (col + 1 < NREAL) {
                float v = y + __ldg(&bias[col+1]);
                if (RELU) v = fmaxf(v, 0.f);
                C[row*sc + col + 1] = v;
            }
        }
    __syncthreads();
}

// ---------------------------------------------------------------------------
// Event generators
// ---------------------------------------------------------------------------
struct EventGenA {          // phase 1a: c in [0,176), all 48 rows
    const int*   edge_idx;
    const float* edge_embed;
    const float* edge_identify;
    const float* t_records;
    const float* basis_freq;
    const float* phase;
    int g0;
    __device__ __forceinline__ void operator()(float* Abuf, int kc, int tid) const {
        for (int idx = tid; idx < ROWS*44; idx += NTHREADS) {
            int r = idx / 44, cc = idx - r*44;
            int c = kc + cc;
            int p = r / 3, l = r - p*3;
            int g = g0 + p;
            float v = 0.f;
            if (c < 172) {
                int e = __ldg(&edge_idx[g*3 + l]);
                v = __ldg(&edge_embed[(long)e*172 + c]);
            } else if (c < 175) {
                v = __ldg(&edge_identify[(g*3 + l)*3 + (c - 172)]);
            } else if (c == 175) {
                float dt = __ldg(&t_records[g*3 + 2]) - __ldg(&t_records[g*3 + l]);
                v = __cosf(dt * __ldg(&basis_freq[0]) + __ldg(&phase[0]));
            }
            Abuf[idx] = v;
        }
    }
};

struct EventGenB {          // phase 1b: c = 176 + k2 in [176,347), 32 rows (l != 2)
    const float* t_records;
    const float* basis_freq;
    const float* phase;
    int g0;
    __device__ __forceinline__ void operator()(float* Abuf, int kc, int tid) const {
        for (int idx = tid; idx < 32*44; idx += NTHREADS) {
            int rr = idx / 44, cc = idx - rr*44;
            int c = 176 + kc + cc;
            int p = rr >> 1, l = rr & 1;
            int g = g0 + p;
            float v = 0.f;
            if (c < 347) {
                int d = c - 175;
                float dt = __ldg(&t_records[g*3 + 2]) - __ldg(&t_records[g*3 + l]);
                v = __cosf(dt * __ldg(&basis_freq[d]) + __ldg(&phase[d]));
            }
            Abuf[idx] = v;
        }
    }
};

// Phase 1a GEMM: K=176 (4 chunks of 44), RT=6, P=3, writes evt (+bias).
__device__ __forceinline__ void gemm_event_a(
    const float* __restrict__ bias,
    float* __restrict__ Abuf, const EventGenA& gen,
    float* __restrict__ C, int tid)
{
    const int ty = tid >> 5, tx = tid & 31;
    ull acc[6][3];
#pragma unroll
    for (int i = 0; i < 6; i++)
#pragma unroll
        for (int g = 0; g < 3; g++) acc[i][g] = 0ull;

    gen(Abuf, 0, tid);
    __syncthreads();
#pragma unroll 1
    for (int kc = 0; kc < 176; kc += 44) {
        int buf = (kc / 44) & 1;
        const float* cur = Abuf + buf*2112;
        if (kc + 44 < 176) gen(Abuf + (buf^1)*2112, kc + 44, tid);
        const float* wq   = g_WT_event + kc*192 + 2*tx;
        const float* arow = cur + ty*6*44;
#pragma unroll 1
        for (int k4 = 0; k4 < 44; k4 += 4) {
            float4 av[6];
#pragma unroll
            for (int i = 0; i < 6; i++)
                av[i] = *reinterpret_cast<const float4*>(arow + i*44 + k4);
#pragma unroll
            for (int kk = 0; kk < 4; kk++) {
                ull w[3];
#pragma unroll
                for (int g = 0; g < 3; g++)
                    w[g] = __ldg(reinterpret_cast<const ull*>(wq + (k4+kk)*192 + g*64));
#pragma unroll
                for (int i = 0; i < 6; i++) {
                    float a = fsel4(av[i], kk);
                    ull ad = pack2(a, a);
#pragma unroll
                    for (int g = 0; g < 3; g++) fma2(acc[i][g], ad, w[g]);
                }
            }
        }
        __syncthreads();
    }
#pragma unroll
    for (int i = 0; i < 6; i++)
#pragma unroll
        for (int g = 0; g < 3; g++) {
            int col = g*64 + 2*tx;
            float x, y; unpack2(acc[i][g], x, y);
            int row = ty*6 + i;
            if (col < 172)     C[row*176 + col]     = x + __ldg(&bias[col]);
            if (col + 1 < 172) C[row*176 + col + 1] = y + __ldg(&bias[col+1]);
        }
    __syncthreads();
}

// Phase 1b GEMM: K=176 (weights rows 176..351), RT=4 over 32 rows, accumulates
// into evt at rows (rr>>1)*3 + (rr&1).
__device__ __forceinline__ void gemm_event_b(
    float* __restrict__ Abuf, const EventGenB& gen,
    float* __restrict__ C, int tid)
{
    const int ty = tid >> 5, tx = tid & 31;
    ull acc[4][3];
#pragma unroll
    for (int i = 0; i < 4; i++)
#pragma unroll
        for (int g = 0; g < 3; g++) acc[i][g] = 0ull;

    gen(Abuf, 0, tid);
    __syncthreads();
#pragma unroll 1
    for (int kc = 0; kc < 176; kc += 44) {
        int buf = (kc / 44) & 1;
        const float* cur = Abuf + buf*2112;
        if (kc + 44 < 176) gen(Abuf + (buf^1)*2112, kc + 44, tid);
        const float* wq   = g_WT_event + (176 + kc)*192 + 2*tx;
        const float* arow = cur + ty*4*44;
#pragma unroll 1
        for (int k4 = 0; k4 < 44; k4 += 4) {
            float4 av[4];
#pragma unroll
            for (int i = 0; i < 4; i++)
                av[i] = *reinterpret_cast<const float4*>(arow + i*44 + k4);
#pragma unroll
            for (int kk = 0; kk < 4; kk++) {
                ull w[3];
#pragma unroll
                for (int g = 0; g < 3; g++)
                    w[g] = __ldg(reinterpret_cast<const ull*>(wq + (k4+kk)*192 + g*64));
#pragma unroll
                for (int i = 0; i < 4; i++) {
                    float a = fsel4(av[i], kk);
                    ull ad = pack2(a, a);
#pragma unroll
                    for (int g = 0; g < 3; g++) fma2(acc[i][g], ad, w[g]);
                }
            }
        }
        __syncthreads();
    }
#pragma unroll
    for (int i = 0; i < 4; i++)
#pragma unroll
        for (int g = 0; g < 3; g++) {
            int col = g*64 + 2*tx;
            float x, y; unpack2(acc[i][g], x, y);
            int rr = ty*4 + i;
            int row = (rr >> 1)*3 + (rr & 1);
            if (col < 172)     C[row*176 + col]     += x;
            if (col + 1 < 172) C[row*176 + col + 1] += y;
        }
    __syncthreads();
}

// ---------------------------------------------------------------------------
// Dual gine (R6)
// ---------------------------------------------------------------------------
struct GineDualGen {
    const int*   node_idx;
    const float* node_embed;
    const float* evt;   // smem, pitch 176
    int g0;
    __device__ __forceinline__ void operator()(float* Abuf, int kc, int tid) const {
        for (int idx = tid; idx < ROWS*44; idx += NTHREADS) {
            int r = idx / 44, cc = idx - r*44;
            int c = kc + cc;
            int p = r / 3, l = r - p*3;
            int g = g0 + p;
            float v1 = 0.f, v2 = 0.f;
            if (c < 172) {
                int ns = __ldg(&node_idx[g*6 + 2*l]);
                int nt = __ldg(&node_idx[g*6 + 2*l + 1]);
                float s = __ldg(&node_embed[(long)ns*172 + c]);
                float t = __ldg(&node_embed[(long)nt*172 + c]);
                float e = evt[r*176 + c];
                v1 = s + fmaxf(t + e, 0.f);
                v2 = t + fmaxf(s + e, 0.f);
            }
            Abuf[idx]        = v1;
            Abuf[2112 + idx] = v2;
        }
    }
};

__device__ __forceinline__ void gemm_gine_dual(
    const float* __restrict__ bias,
    float* __restrict__ Abuf, const GineDualGen& gen,
    float* __restrict__ C1, float* __restrict__ C2, int tid)
{
    const int ty = tid >> 5, tx = tid & 31;
    ull acc1[6], acc2[6];
#pragma unroll
    for (int i = 0; i < 6; i++) { acc1[i] = 0ull; acc2[i] = 0ull; }
#pragma unroll 1
    for (int kc = 0; kc < 176; kc += 44) {
        __syncthreads();
        gen(Abuf, kc, tid);
        __syncthreads();
        const float* wq = g_WT_gcn1 + kc*64 + 2*tx;
        const float* a1row = Abuf + ty*6*44;
        const float* a2row = Abuf + 2112 + ty*6*44;
#pragma unroll 1
        for (int k4 = 0; k4 < 44; k4 += 4) {
            ull w[4];
#pragma unroll
            for (int kk = 0; kk < 4; kk++)
                w[kk] = __ldg(reinterpret_cast<const ull*>(wq + (k4+kk)*64));
#pragma unroll
            for (int i = 0; i < 6; i++) {
                float4 a1 = *reinterpret_cast<const float4*>(a1row + i*44 + k4);
                float4 a2 = *reinterpret_cast<const float4*>(a2row + i*44 + k4);
#pragma unroll
                for (int kk = 0; kk < 4; kk++) {
                    fma2(acc1[i], pack2(fsel4(a1,kk), fsel4(a1,kk)), w[kk]);
                    fma2(acc2[i], pack2(fsel4(a2,kk), fsel4(a2,kk)), w[kk]);
                }
            }
        }
    }
    int col = 2*tx;
    float b0 = __ldg(&bias[col]), b1 = __ldg(&bias[col+1]);
#pragma unroll
    for (int i = 0; i < 6; i++) {
        int row = ty*6 + i;
        float x, y;
        unpack2(acc1[i], x, y);
        C1[row*64 + col]     = fmaxf(x + b0, 0.f);
        C1[row*64 + col + 1] = fmaxf(y + b1, 0.f);
        unpack2(acc2[i], x, y);
        C2[row*64 + col]     = fmaxf(x + b0, 0.f);
        C2[row*64 + col + 1] = fmaxf(y + b1, 0.f);
    }
    __syncthreads();
}

__device__ __forceinline__ void gemm_gcn2_dual(
    const float* __restrict__ bias,
    const float* __restrict__ H1, const float* __restrict__ H2,
    float* __restrict__ feat, int tid)
{
    const int ty = tid >> 5, tx = tid & 31;
    ull acc1[6], acc2[6];
#pragma unroll
    for (int i = 0; i < 6; i++) { acc1[i] = 0ull; acc2[i] = 0ull; }
    const float* wq = g_WT_gcn2 + 2*tx;
#pragma unroll 1
    for (int k4 = 0; k4 < 64; k4 += 4) {
        ull w[4];
#pragma unroll
        for (int kk = 0; kk < 4; kk++)
            w[kk] = __ldg(reinterpret_cast<const ull*>(wq + (k4+kk)*64));
#pragma unroll
        for (int i = 0; i < 6; i++) {
            float4 a1 = *reinterpret_cast<const float4*>(H1 + (ty*6+i)*64 + k4);
            float4 a2 = *reinterpret_cast<const float4*>(H2 + (ty*6+i)*64 + k4);
#pragma unroll
            for (int kk = 0; kk < 4; kk++) {
                fma2(acc1[i], pack2(fsel4(a1,kk), fsel4(a1,kk)), w[kk]);
                fma2(acc2[i], pack2(fsel4(a2,kk), fsel4(a2,kk)), w[kk]);
            }
        }
    }
    __syncthreads();
    int col = 2*tx;
    float b0 = __ldg(&bias[col]), b1 = __ldg(&bias[col+1]);
#pragma unroll
    for (int i = 0; i < 6; i++) {
        int row = ty*6 + i;
        float x, y;
        unpack2(acc1[i], x, y);
        feat[row*128 + col]      = x + b0;
        feat[row*128 + col + 1]  = y + b1;
        unpack2(acc2[i], x, y);
        feat[row*128 + 64 + col]     = x + b0;
        feat[row*128 + 64 + col + 1] = y + b1;
    }
    __syncthreads();
}

// ---------------------------------------------------------------------------
// Fused main kernel
// ---------------------------------------------------------------------------
__global__ void __launch_bounds__(NTHREADS, 3)
fused_kernel(const int*   __restrict__ node_idx,
             const int*   __restrict__ edge_idx,
             const int*   __restrict__ cat_feat,
             const float* __restrict__ t_records,
             const float* __restrict__ edge_identify,
             const float* __restrict__ node_embed,
             const float* __restrict__ edge_embed,
             const float* __restrict__ basis_freq,
             const float* __restrict__ phase,
             const float* __restrict__ lin_event_b,
             const float* __restrict__ gcn_b1,
             const float* __restrict__ gcn_b2,
             const float* __restrict__ att_w1_b,
             const float* __restrict__ att_w2_b,
             const float* __restrict__ att_m1_b,
             const float* __restrict__ att_m2_b,
             const float* __restrict__ mlp_b1,
             const float* __restrict__ mlp_b2,
             const float* __restrict__ mlp_w3,
             const float* __restrict__ mlp_b3,
             float*       __restrict__ out)
{
    extern __shared__ float sm[];
    const int tid = threadIdx.x;
    const int g0  = blockIdx.x * PAIRS;

    float* evt  = sm + EVT_OFF;
    float* feat = sm + FEAT_OFF;
    float* Abuf = sm + ABUF_OFF;

    // ---- Phase 1a: event cols [0,176), all rows ----
    EventGenA ega{edge_idx, edge_embed, edge_identify, t_records, basis_freq, phase, g0};
    gemm_event_a(lin_event_b, Abuf, ega, evt, tid);

    // ---- Phase 1b: event cols [176,347), only l!=2 rows ----
    EventGenB egb{t_records, basis_freq, phase, g0};
    gemm_event_b(Abuf, egb, evt, tid);

    // ---- Phase 1c: l=2 rows get precomputed time-part constant ----
    for (int idx = tid; idx < PAIRS*172; idx += NTHREADS) {
        int p = idx / 172, c = idx - p*172;
        evt[(p*3 + 2)*176 + c] += __ldg(&g_ct2[c]);
    }
    __syncthreads();

    // ---- Phase 2: dual gine -> GH1/GH2 ----
    GineDualGen gg{node_idx, node_embed, evt, g0};
    gemm_gine_dual(gcn_b1, Abuf, gg, sm + GH1_OFF, sm + GH2_OFF, tid);

    // ---- Phase 3: dual gcn2 -> feat ----
    gemm_gcn2_dual(gcn_b2, sm + GH1_OFF, sm + GH2_OFF, feat, tid);

    // ---- Phase 4: attention ----
    float* tgtb = sm + TGTB_OFF;
    for (int idx = tid; idx < 32*128; idx += NTHREADS) {
        int r = idx >> 7, c = idx & 127;
        tgtb[idx] = feat[((r >> 1)*3 + (r & 1))*128 + c];
    }
    __syncthreads();
    float* Wq = sm + WQ_OFF;
    gemm_direct<128,128,4,2,false,128>(g_WT_att2, att_w2_b, tgtb, 128, Wq, 128, tid);
    float* Wp = sm + WP_OFF;
    gemm_direct<128,128,2,2,false,128>(g_WT_att1, att_w1_b, feat + 256, 384, Wp, 128, tid);

    float* scb = sm + SC_OFF;
    {
        int pk = tid >> 3, sub = tid & 7;
        int p = pk >> 1, k = pk & 1;
        float s = 0.f;
        for (int j = sub; j < 128; j += 8)
            s += Wp[p*128 + j] * Wq[(2*p + k)*128 + j];
        s += __shfl_down_sync(0xffffffffu, s, 4, 8);
        s += __shfl_down_sync(0xffffffffu, s, 2, 8);
        s += __shfl_down_sync(0xffffffffu, s, 1, 8);
        if (sub == 0) scb[pk] = s;
    }
    __syncthreads();
    if (tid < PAIRS) {
        float s0 = scb[2*tid], s1 = scb[2*tid + 1];
        float m = fmaxf(s0, s1);
        float e0 = __expf(s0 - m), e1 = __expf(s1 - m);
        float inv = 1.f / (e0 + e1);
        scb[2*tid]     = e0 * inv;
        scb[2*tid + 1] = e1 * inv;
    }
    __syncthreads();
    float* outb = sm + OUTB_OFF;
    for (int idx = tid; idx < PAIRS*128; idx += NTHREADS) {
        int p = idx >> 7, c = idx & 127;
        outb[idx] = feat[(p*3 + 2)*128 + c]
                  + scb[2*p]     * Wq[(2*p)*128 + c]
                  + scb[2*p + 1] * Wq[(2*p + 1)*128 + c];
    }
    __syncthreads();

    float* hb = sm + HB_OFF;
    float* sf = sm + SF_OFF;
    gemm_direct<64,128,2,1,true,64>(g_WT_m1, att_m1_b, outb, 128, hb, 64, tid);
    gemm_direct<64,64,2,1,false,64>(g_WT_m2, att_m2_b, hb, 64, sf, 64, tid);

    // ---- Phase 5: MLP tail as coalesced GEMMs ----
    float* xb  = sm + XB_OFF;
    float* h1b = sm + H1_OFF;
    float* h2b = sm + H2_OFF;
    for (int idx = tid; idx < PAIRS*76; idx += NTHREADS) {
        int p = idx / 76, c = idx - p*76;
        float v;
        if (c < 64) v = sf[p*64 + c];
        else        v = (__ldg(&cat_feat[g0 + p]) == (c - 64)) ? 1.f : 0.f;
        xb[idx] = v;
    }
    __syncthreads();
    gemm_direct<128,76,2,2,true,76>(g_WT_mlp1, mlp_b1, xb, 76, h1b, 76, tid);
    gemm_direct<64,76,2,1,true,64>(g_WT_mlp2, mlp_b2, h1b, 76, h2b, 64, tid);

    if (tid < PAIRS) {
        float z = __ldg(&mlp_b3[0]);
        const float* x = h2b + tid*64;
#pragma unroll 4
        for (int k = 0; k < 64; k++) z += x[k] * __ldg(&mlp_w3[k]);
        out[g0 + tid] = 1.f / (1.f + __expf(-z));
    }
}

// ---------------------------------------------------------------------------
// Launch
// ---------------------------------------------------------------------------
extern "C" void kernel_launch(void* const* d_in, const int* in_sizes, int n_in,
                              void* d_out, int out_size)
{
    const int*   node_idx      = (const int*)  d_in[0];
    const int*   edge_idx      = (const int*)  d_in[1];
    const int*   cat_feat      = (const int*)  d_in[2];
    const float* t_records     = (const float*)d_in[3];
    const float* edge_identify = (const float*)d_in[4];
    // d_in[5] = cut_time_l (unused by reference)
    const float* node_embed    = (const float*)d_in[6];
    const float* edge_embed    = (const float*)d_in[7];
    const float* basis_freq    = (const float*)d_in[8];
    const float* phase         = (const float*)d_in[9];
    const float* lin_event_w   = (const float*)d_in[10];
    const float* lin_event_b   = (const float*)d_in[11];
    const float* gcn_w1        = (const float*)d_in[12];
    const float* gcn_b1        = (const float*)d_in[13];
    const float* gcn_w2        = (const float*)d_in[14];
    const float* gcn_b2        = (const float*)d_in[15];
    const float* att_w1_w      = (const float*)d_in[16];
    const float* att_w1_b      = (const float*)d_in[17];
    const float* att_w2_w      = (const float*)d_in[18];
    const float* att_w2_b      = (const float*)d_in[19];
    const float* att_m1_w      = (const float*)d_in[20];
    const float* att_m1_b      = (const float*)d_in[21];
    const float* att_m2_w      = (const float*)d_in[22];
    const float* att_m2_b      = (const float*)d_in[23];
    const float* mlp_w1        = (const float*)d_in[24];
    const float* mlp_b1        = (const float*)d_in[25];
    const float* mlp_w2        = (const float*)d_in[26];
    const float* mlp_b2        = (const float*)d_in[27];
    const float* mlp_w3        = (const float*)d_in[28];
    const float* mlp_b3        = (const float*)d_in[29];
    float* outp = (float*)d_out;

    cudaFuncSetAttribute(fused_kernel,
                         cudaFuncAttributeMaxDynamicSharedMemorySize, SMEM_BYTES);

    prep_kernel<<<128, 256>>>(lin_event_w, gcn_w1, gcn_w2,
                              att_w1_w, att_w2_w, att_m1_w, att_m2_w,
                              mlp_w1, mlp_w2, phase);

    fused_kernel<<<NBLK, NTHREADS, SMEM_BYTES>>>(
        node_idx, edge_idx, cat_feat, t_records, edge_identify,
        node_embed, edge_embed, basis_freq, phase,
        lin_event_b, gcn_b1, gcn_b2,
        att_w1_b, att_w2_b, att_m1_b, att_m2_b,
        mlp_b1, mlp_b2, mlp_w3, mlp_b3,
        outp);
}